// round 2
// baseline (speedup 1.0000x reference)
#include <cuda_runtime.h>
#include <cuda_bf16.h>
#include <math.h>
#include <stdint.h>

// ---------------- problem constants ----------------
#define BB 4
#define NN 2048
#define KK 20
#define PTS (BB*NN)          // 8192
#define SLOPE 0.2f
#define EPS_BN 1e-5f

// ---------------- device scratch (no allocs allowed) ----------------
__device__ float g_F0[PTS*3];
__device__ float g_F1[PTS*64];
__device__ float g_F2[PTS*64];
__device__ float g_F3[PTS*128];
__device__ float g_F4[PTS*256];
__device__ float g_negd[(size_t)BB*NN*NN];   // 67MB
__device__ int   g_idx[PTS*KK];
__device__ float g_Y[PTS*512];               // transform out, max 2*O = 512
__device__ float g_Wcat[512*128];            // max (2O=512) x (C=128)
__device__ float g_sq[PTS];
__device__ float g_Y5[PTS*1024];             // 33.5MB

// ---------------- transpose (B,3,N) -> (B,N,3) ----------------
__global__ void transpose_in(const float* __restrict__ x, float* __restrict__ F0) {
    int t = blockIdx.x*blockDim.x + threadIdx.x;
    if (t >= BB*3*NN) return;
    int b = t / (3*NN);
    int rem = t % (3*NN);
    int c = rem / NN, n = rem % NN;
    F0[(size_t)(b*NN + n)*3 + c] = x[t];
}

// ---------------- squared norms per point ----------------
__global__ void sqnorm_kernel(const float* __restrict__ F, float* __restrict__ sq, int C) {
    int p = blockIdx.x*blockDim.x + threadIdx.x;
    if (p >= PTS) return;
    const float* f = F + (size_t)p*C;
    float s = 0.f;
    for (int c = 0; c < C; ++c) s = fmaf(f[c], f[c], s);
    sq[p] = s;
}

// ---------------- generic NT GEMM: C[i][j] = sum_k A[i*K+k]*Bt[j*K+k] ----------
// epi=1: C = -((sq[i]+sq[j]) - 2*acc)   (pairwise neg-distance)
__global__ __launch_bounds__(256)
void gemm_nt(const float* __restrict__ A, const float* __restrict__ Bt,
             float* __restrict__ Cmat, int M, int Nc, int K,
             size_t sA, size_t sB, size_t sC,
             const float* __restrict__ sq, int Nsq, int epi)
{
    int bz = blockIdx.z;
    A    += (size_t)bz * sA;
    Bt   += (size_t)bz * sB;
    Cmat += (size_t)bz * sC;

    __shared__ float As[16][68];
    __shared__ float Bs[16][68];

    int tid = threadIdx.x;          // 256 threads
    int tx = tid & 15;              // col group
    int ty = tid >> 4;              // row group
    int i0 = blockIdx.y * 64;
    int j0 = blockIdx.x * 64;

    int lr = tid >> 4;              // loader row base (0..15)
    int lc = tid & 15;              // loader k

    float acc[4][4];
    #pragma unroll
    for (int i = 0; i < 4; ++i)
        #pragma unroll
        for (int j = 0; j < 4; ++j) acc[i][j] = 0.f;

    for (int k0 = 0; k0 < K; k0 += 16) {
        bool kin = (k0 + lc) < K;
        #pragma unroll
        for (int u = 0; u < 4; ++u) {
            int row = lr + 16*u;
            float va = kin ? A [(size_t)(i0+row)*K + k0 + lc] : 0.f;
            float vb = kin ? Bt[(size_t)(j0+row)*K + k0 + lc] : 0.f;
            As[lc][row] = va;
            Bs[lc][row] = vb;
        }
        __syncthreads();
        #pragma unroll
        for (int k = 0; k < 16; ++k) {
            float4 a4 = *(const float4*)(&As[k][ty*4]);
            float4 b4 = *(const float4*)(&Bs[k][tx*4]);
            float av[4] = {a4.x, a4.y, a4.z, a4.w};
            float bv[4] = {b4.x, b4.y, b4.z, b4.w};
            #pragma unroll
            for (int ii = 0; ii < 4; ++ii)
                #pragma unroll
                for (int jj = 0; jj < 4; ++jj)
                    acc[ii][jj] = fmaf(av[ii], bv[jj], acc[ii][jj]);
        }
        __syncthreads();
    }

    const float* sqr = (epi) ? (sq + (size_t)bz * Nsq) : nullptr;
    #pragma unroll
    for (int ii = 0; ii < 4; ++ii) {
        int gi = i0 + ty*4 + ii;
        float si = epi ? sqr[gi] : 0.f;
        #pragma unroll
        for (int jj = 0; jj < 4; ++jj) {
            int gj = j0 + tx*4 + jj;
            float v = acc[ii][jj];
            if (epi) {
                float t = (si + sqr[gj]) - 2.0f*v;
                v = -t;
            }
            Cmat[(size_t)gi*Nc + gj] = v;
        }
    }
}

// ---------------- top-20 per row (value desc, index-asc tie-break) ----------
__global__ __launch_bounds__(256)
void topk_kernel(const float* __restrict__ negd, int* __restrict__ idx_out)
{
    int row = blockIdx.x;                        // b*N + n
    const float* d = negd + (size_t)row * NN;
    __shared__ float vals[NN];
    __shared__ unsigned long long wkey[8];
    int t = threadIdx.x;

    for (int j = t; j < NN; j += 256) vals[j] = d[j];
    __syncthreads();

    for (int r = 0; r < KK; ++r) {
        unsigned long long best = 0ull;
        #pragma unroll
        for (int u = 0; u < NN/256; ++u) {
            int j = t + u*256;
            float v = vals[j];
            unsigned int ub = __float_as_uint(v);
            ub = (ub & 0x80000000u) ? ~ub : (ub | 0x80000000u);  // ordered-float
            unsigned long long key =
                ((unsigned long long)ub << 32) | (unsigned int)(~j);
            best = (key > best) ? key : best;
        }
        #pragma unroll
        for (int o = 16; o; o >>= 1) {
            unsigned long long other = __shfl_xor_sync(0xffffffffu, best, o);
            best = (other > best) ? other : best;
        }
        if ((t & 31) == 0) wkey[t >> 5] = best;
        __syncthreads();
        if (t < 8) {
            unsigned long long b2 = wkey[t];
            #pragma unroll
            for (int o = 4; o; o >>= 1) {
                unsigned long long other = __shfl_xor_sync(0xffu, b2, o);
                b2 = (other > b2) ? other : b2;
            }
            if (t == 0) {
                int win = (int)(~(unsigned int)(b2 & 0xffffffffull));
                idx_out[row*KK + r] = win;
                vals[win] = -INFINITY;
            }
        }
        __syncthreads();
    }
}

// ---------------- build Wcat = [W_left ; W_right - W_left] ----------------
__global__ void prep_wcat(const float* __restrict__ W, float* __restrict__ Wcat,
                          int O, int C)
{
    int t = blockIdx.x*blockDim.x + threadIdx.x;
    if (t >= 2*O*C) return;
    int j = t / C, c = t % C;
    float v;
    if (j < O) v = W[(size_t)j*2*C + c];
    else {
        int o = j - O;
        v = W[(size_t)o*2*C + C + c] - W[(size_t)o*2*C + c];
    }
    Wcat[t] = v;
}

// ---------------- edge feature max-pool over k ----------------
// Y: (PTS, 2O) rows; cols [0,O) = W_l@x (neighbor term), [O,2O) = (W_r-W_l)@x (center term)
__global__ void edge_max(const float* __restrict__ Y, const int* __restrict__ idx,
                         const float* __restrict__ gam, const float* __restrict__ bet,
                         float* __restrict__ Fout, int O)
{
    int p = blockIdx.x;          // b*N + n
    int b = p >> 11;             // /2048
    int o = threadIdx.x;
    __shared__ int sidx[KK];
    if (o < KK) sidx[o] = idx[p*KK + o];
    __syncthreads();

    float s    = gam[o] / sqrtf(1.0f + EPS_BN);
    float bias = bet[o];
    float cc   = Y[(size_t)p*(2*O) + O + o];
    float best = -INFINITY;
    #pragma unroll 5
    for (int k = 0; k < KK; ++k) {
        int m = sidx[k];
        float a = Y[((size_t)(b*NN + m))*(2*O) + o];
        float y = s*(a + cc) + bias;
        y = (y >= 0.f) ? y : SLOPE*y;
        best = fmaxf(best, y);
    }
    Fout[(size_t)p*O + o] = best;
}

// ---------------- final: max over N of lrelu(affine(Y5)) ----------------
__global__ void final_max(const float* __restrict__ Y5, const float* __restrict__ gam,
                          const float* __restrict__ bet, float* __restrict__ out)
{
    int b = blockIdx.x;
    int o = blockIdx.y * 256 + threadIdx.x;       // 0..1023
    float s    = gam[o] / sqrtf(1.0f + EPS_BN);
    float bias = bet[o];
    const float* y = Y5 + (size_t)b*NN*1024 + o;
    float best = -INFINITY;
    for (int n = 0; n < NN; ++n) {
        float v = s * y[(size_t)n*1024] + bias;
        v = (v >= 0.f) ? v : SLOPE*v;
        best = fmaxf(best, v);
    }
    out[b*1024 + o] = best;
}

// ---------------- launch ----------------
extern "C" void kernel_launch(void* const* d_in, const int* in_sizes, int n_in,
                              void* d_out, int out_size)
{
    const float* x = (const float*)d_in[0];
    const float* W[5]; const float* G[5]; const float* Bv[5];

    // setup_inputs() inserts per-layer triplets: x, W1,g1,b1, W2,g2,b2, ...
    // Detect layout from sizes as a safety net (grouped would have
    // in_sizes[2] == 8192 (W2) instead of 64 (g1)).
    bool interleaved = (n_in >= 4 && in_sizes[2] == in_sizes[3]);
    if (interleaved) {
        for (int i = 0; i < 5; ++i) {
            W[i]  = (const float*)d_in[1 + 3*i];
            G[i]  = (const float*)d_in[2 + 3*i];
            Bv[i] = (const float*)d_in[3 + 3*i];
        }
    } else {
        for (int i = 0; i < 5; ++i) {
            W[i]  = (const float*)d_in[1 + i];
            G[i]  = (const float*)d_in[6 + i];
            Bv[i] = (const float*)d_in[11 + i];
        }
    }
    float* out = (float*)d_out;

    float *F0,*F1,*F2,*F3,*F4,*negd,*Y,*Wcat,*sq,*Y5; int* idx;
    cudaGetSymbolAddress((void**)&F0,   g_F0);
    cudaGetSymbolAddress((void**)&F1,   g_F1);
    cudaGetSymbolAddress((void**)&F2,   g_F2);
    cudaGetSymbolAddress((void**)&F3,   g_F3);
    cudaGetSymbolAddress((void**)&F4,   g_F4);
    cudaGetSymbolAddress((void**)&negd, g_negd);
    cudaGetSymbolAddress((void**)&Y,    g_Y);
    cudaGetSymbolAddress((void**)&Wcat, g_Wcat);
    cudaGetSymbolAddress((void**)&sq,   g_sq);
    cudaGetSymbolAddress((void**)&Y5,   g_Y5);
    cudaGetSymbolAddress((void**)&idx,  g_idx);

    transpose_in<<<(BB*3*NN + 255)/256, 256>>>(x, F0);

    struct Layer { const float* Fin; float* Fout; int C; int O; int wi; };
    Layer L[4] = {
        {F0, F1,   3,  64, 0},
        {F1, F2,  64,  64, 1},
        {F2, F3,  64, 128, 2},
        {F3, F4, 128, 256, 3},
    };

    for (int li = 0; li < 4; ++li) {
        int C = L[li].C, O = L[li].O;
        sqnorm_kernel<<<PTS/256, 256>>>(L[li].Fin, sq, C);
        // pairwise neg-distance: per-batch A·Aᵀ
        gemm_nt<<<dim3(NN/64, NN/64, BB), 256>>>(
            L[li].Fin, L[li].Fin, negd, NN, NN, C,
            (size_t)NN*C, (size_t)NN*C, (size_t)NN*NN, sq, NN, 1);
        topk_kernel<<<PTS, 256>>>(negd, idx);
        prep_wcat<<<(2*O*C + 255)/256, 256>>>(W[L[li].wi], Wcat, O, C);
        // transform: Y = F @ Wcatᵀ  -> (PTS, 2O)
        gemm_nt<<<dim3(2*O/64, PTS/64, 1), 256>>>(
            L[li].Fin, Wcat, Y, PTS, 2*O, C, 0, 0, 0, nullptr, 0, 0);
        edge_max<<<PTS, O>>>(Y, idx, G[L[li].wi], Bv[L[li].wi], L[li].Fout, O);
    }

    // final conv 256 -> 1024, then max over N
    gemm_nt<<<dim3(1024/64, PTS/64, 1), 256>>>(
        F4, W[4], Y5, PTS, 1024, 256, 0, 0, 0, nullptr, 0, 0);
    final_max<<<dim3(BB, 1024/256), 256>>>(Y5, G[4], Bv[4], out);
}

// round 3
// speedup vs baseline: 1.5373x; 1.5373x over previous
#include <cuda_runtime.h>
#include <cuda_bf16.h>
#include <math.h>
#include <stdint.h>

// ---------------- problem constants ----------------
#define BB 4
#define NN 2048
#define KK 20
#define PTS (BB*NN)          // 8192
#define SLOPE 0.2f
#define EPS_BN 1e-5f

// ---------------- device scratch (no allocs allowed) ----------------
__device__ float g_F0[PTS*3];
__device__ float g_F1[PTS*64];
__device__ float g_F2[PTS*64];
__device__ float g_F3[PTS*128];
__device__ float g_F4[PTS*256];
__device__ float g_negd[(size_t)BB*NN*NN];   // 67MB
__device__ int   g_idx[PTS*KK];
__device__ float g_Y[PTS*512];               // transform out, max 2*O = 512
__device__ float g_Wcat[512*128];            // max (2O=512) x (C=128)
__device__ float g_sq[PTS];
__device__ float g_Y5[PTS*1024];             // 33.5MB

// ---------------- transpose (B,3,N) -> (B,N,3) ----------------
__global__ void transpose_in(const float* __restrict__ x, float* __restrict__ F0) {
    int t = blockIdx.x*blockDim.x + threadIdx.x;
    if (t >= BB*3*NN) return;
    int b = t / (3*NN);
    int rem = t % (3*NN);
    int c = rem / NN, n = rem % NN;
    F0[(size_t)(b*NN + n)*3 + c] = x[t];
}

// ---------------- squared norms per point ----------------
__global__ void sqnorm_kernel(const float* __restrict__ F, float* __restrict__ sq, int C) {
    int p = blockIdx.x*blockDim.x + threadIdx.x;
    if (p >= PTS) return;
    const float* f = F + (size_t)p*C;
    float s = 0.f;
    for (int c = 0; c < C; ++c) s = fmaf(f[c], f[c], s);
    sq[p] = s;
}

// ---------------- generic NT GEMM: C[i][j] = sum_k A[i*K+k]*Bt[j*K+k] ----------
// epi=1: C = -((sq[i]+sq[j]) - 2*acc)   (pairwise neg-distance)
__global__ __launch_bounds__(256)
void gemm_nt(const float* __restrict__ A, const float* __restrict__ Bt,
             float* __restrict__ Cmat, int M, int Nc, int K,
             size_t sA, size_t sB, size_t sC,
             const float* __restrict__ sq, int Nsq, int epi)
{
    int bz = blockIdx.z;
    A    += (size_t)bz * sA;
    Bt   += (size_t)bz * sB;
    Cmat += (size_t)bz * sC;

    __shared__ float As[16][68];
    __shared__ float Bs[16][68];

    int tid = threadIdx.x;          // 256 threads
    int tx = tid & 15;              // col group
    int ty = tid >> 4;              // row group
    int i0 = blockIdx.y * 64;
    int j0 = blockIdx.x * 64;

    int lr = tid >> 4;              // loader row base (0..15)
    int lc = tid & 15;              // loader k

    float acc[4][4];
    #pragma unroll
    for (int i = 0; i < 4; ++i)
        #pragma unroll
        for (int j = 0; j < 4; ++j) acc[i][j] = 0.f;

    for (int k0 = 0; k0 < K; k0 += 16) {
        bool kin = (k0 + lc) < K;
        #pragma unroll
        for (int u = 0; u < 4; ++u) {
            int row = lr + 16*u;
            float va = kin ? A [(size_t)(i0+row)*K + k0 + lc] : 0.f;
            float vb = kin ? Bt[(size_t)(j0+row)*K + k0 + lc] : 0.f;
            As[lc][row] = va;
            Bs[lc][row] = vb;
        }
        __syncthreads();
        #pragma unroll
        for (int k = 0; k < 16; ++k) {
            float4 a4 = *(const float4*)(&As[k][ty*4]);
            float4 b4 = *(const float4*)(&Bs[k][tx*4]);
            float av[4] = {a4.x, a4.y, a4.z, a4.w};
            float bv[4] = {b4.x, b4.y, b4.z, b4.w};
            #pragma unroll
            for (int ii = 0; ii < 4; ++ii)
                #pragma unroll
                for (int jj = 0; jj < 4; ++jj)
                    acc[ii][jj] = fmaf(av[ii], bv[jj], acc[ii][jj]);
        }
        __syncthreads();
    }

    const float* sqr = (epi) ? (sq + (size_t)bz * Nsq) : nullptr;
    #pragma unroll
    for (int ii = 0; ii < 4; ++ii) {
        int gi = i0 + ty*4 + ii;
        float si = epi ? sqr[gi] : 0.f;
        #pragma unroll
        for (int jj = 0; jj < 4; ++jj) {
            int gj = j0 + tx*4 + jj;
            float v = acc[ii][jj];
            if (epi) {
                float t = (si + sqr[gj]) - 2.0f*v;
                v = -t;
            }
            Cmat[(size_t)gi*Nc + gj] = v;
        }
    }
}

// ---------------- radix/bin-select top-20 per row ----------------
// Single pass: ordered-uint keys once, 2048-bin histogram on top 11 bits,
// suffix scan for threshold bin, then small argmax rounds only on the
// boundary bin. Tie-break identical to lax.top_k (value desc, index asc)
// via composite u64 key; output order is unordered (set semantics OK:
// downstream max-pools over k).
__global__ __launch_bounds__(256)
void topk_radix(const float* __restrict__ negd, int* __restrict__ idx_out)
{
    int row = blockIdx.x;                        // b*N + n
    const float* d = negd + (size_t)row * NN;

    __shared__ unsigned int hist[2048];
    __shared__ unsigned long long cand[2048];
    __shared__ unsigned int warp_suf[8];
    __shared__ int s_B, s_above, s_nout, s_ncand;
    __shared__ unsigned long long s_best;

    int t = threadIdx.x;

    #pragma unroll
    for (int u = 0; u < 8; ++u) hist[t + 256*u] = 0;
    if (t == 0) { s_nout = 0; s_ncand = 0; }
    __syncthreads();

    unsigned int ukey[8];
    #pragma unroll
    for (int u = 0; u < 8; ++u) {
        int j = t + 256*u;                       // coalesced load
        unsigned int ub = __float_as_uint(d[j]);
        ub = (ub & 0x80000000u) ? ~ub : (ub | 0x80000000u);  // order-preserving
        ukey[u] = ub;
        atomicAdd(&hist[ub >> 21], 1u);
    }
    __syncthreads();

    // thread t owns bins [8t, 8t+8)
    unsigned int local = 0;
    #pragma unroll
    for (int u = 0; u < 8; ++u) local += hist[8*t + u];

    // inclusive suffix scan within warp (x = sum over lanes >= lane)
    unsigned int lane = t & 31, wid = t >> 5;
    unsigned int x = local;
    #pragma unroll
    for (int o = 1; o < 32; o <<= 1) {
        unsigned int y = __shfl_down_sync(0xffffffffu, x, o);
        if (lane + o < 32) x += y;
    }
    unsigned int warp_total = __shfl_sync(0xffffffffu, x, 0);
    if (lane == 0) warp_suf[wid] = warp_total;
    __syncthreads();
    unsigned int above_warp = 0;
    for (int w = wid + 1; w < 8; ++w) above_warp += warp_suf[w];
    unsigned int suffix_above = above_warp + (x - local);   // count in bins above mine

    // find crossing bin: suffix_above(bin) < K <= suffix_above(bin)+hist[bin]
    unsigned int cum = suffix_above;
    #pragma unroll
    for (int u = 7; u >= 0; --u) {
        unsigned int h = hist[8*t + u];
        if (cum < KK && cum + h >= KK) { s_B = 8*t + u; s_above = (int)cum; }
        cum += h;
    }
    __syncthreads();
    int B = s_B;
    int r = KK - s_above;

    // classify: bins > B are winners, bin == B are candidates
    #pragma unroll
    for (int u = 0; u < 8; ++u) {
        int j = t + 256*u;
        int bin = ukey[u] >> 21;
        if (bin > B) {
            int pos = atomicAdd(&s_nout, 1);
            idx_out[row*KK + pos] = j;
        } else if (bin == B) {
            int pos = atomicAdd(&s_ncand, 1);
            cand[pos] = ((unsigned long long)ukey[u] << 32) | (unsigned int)(~j);
        }
    }
    __syncthreads();
    int ncand = s_ncand;
    int base = s_nout;

    // pick top-r from boundary candidates (r small; ncand usually tiny)
    __shared__ unsigned long long wkey[8];
    for (int rr = 0; rr < r; ++rr) {
        unsigned long long best = 0ull;
        for (int j = t; j < ncand; j += 256) {
            unsigned long long k = cand[j];
            best = (k > best) ? k : best;
        }
        #pragma unroll
        for (int o = 16; o; o >>= 1) {
            unsigned long long other = __shfl_xor_sync(0xffffffffu, best, o);
            best = (other > best) ? other : best;
        }
        if ((t & 31) == 0) wkey[t >> 5] = best;
        __syncthreads();
        if (t == 0) {
            unsigned long long b2 = wkey[0];
            #pragma unroll
            for (int w = 1; w < 8; ++w) b2 = (wkey[w] > b2) ? wkey[w] : b2;
            s_best = b2;
            idx_out[row*KK + base + rr] =
                (int)(~(unsigned int)(b2 & 0xffffffffull));
        }
        __syncthreads();
        unsigned long long bb = s_best;
        for (int j = t; j < ncand; j += 256)
            if (cand[j] == bb) cand[j] = 0ull;   // keys unique & >0
        __syncthreads();
    }
}

// ---------------- build Wcat = [W_left ; W_right - W_left] ----------------
__global__ void prep_wcat(const float* __restrict__ W, float* __restrict__ Wcat,
                          int O, int C)
{
    int t = blockIdx.x*blockDim.x + threadIdx.x;
    if (t >= 2*O*C) return;
    int j = t / C, c = t % C;
    float v;
    if (j < O) v = W[(size_t)j*2*C + c];
    else {
        int o = j - O;
        v = W[(size_t)o*2*C + C + c] - W[(size_t)o*2*C + c];
    }
    Wcat[t] = v;
}

// ---------------- edge feature max-pool over k ----------------
__global__ void edge_max(const float* __restrict__ Y, const int* __restrict__ idx,
                         const float* __restrict__ gam, const float* __restrict__ bet,
                         float* __restrict__ Fout, int O)
{
    int p = blockIdx.x;          // b*N + n
    int b = p >> 11;             // /2048
    int o = threadIdx.x;
    __shared__ int sidx[KK];
    if (o < KK) sidx[o] = idx[p*KK + o];
    __syncthreads();

    float s    = gam[o] / sqrtf(1.0f + EPS_BN);
    float bias = bet[o];
    float cc   = Y[(size_t)p*(2*O) + O + o];
    float best = -INFINITY;
    #pragma unroll 5
    for (int k = 0; k < KK; ++k) {
        int m = sidx[k];
        float a = Y[((size_t)(b*NN + m))*(2*O) + o];
        float y = s*(a + cc) + bias;
        y = (y >= 0.f) ? y : SLOPE*y;
        best = fmaxf(best, y);
    }
    Fout[(size_t)p*O + o] = best;
}

// ---------------- final: max over N of lrelu(affine(Y5)) ----------------
__global__ void final_max(const float* __restrict__ Y5, const float* __restrict__ gam,
                          const float* __restrict__ bet, float* __restrict__ out)
{
    int b = blockIdx.x;
    int o = blockIdx.y * 256 + threadIdx.x;       // 0..1023
    float s    = gam[o] / sqrtf(1.0f + EPS_BN);
    float bias = bet[o];
    const float* y = Y5 + (size_t)b*NN*1024 + o;
    float best = -INFINITY;
    for (int n = 0; n < NN; ++n) {
        float v = s * y[(size_t)n*1024] + bias;
        v = (v >= 0.f) ? v : SLOPE*v;
        best = fmaxf(best, v);
    }
    out[b*1024 + o] = best;
}

// ---------------- launch ----------------
extern "C" void kernel_launch(void* const* d_in, const int* in_sizes, int n_in,
                              void* d_out, int out_size)
{
    const float* x = (const float*)d_in[0];
    const float* W[5]; const float* G[5]; const float* Bv[5];

    // inputs are interleaved: x, W1,g1,b1, W2,g2,b2, ... (size-based safety net)
    bool interleaved = (n_in >= 4 && in_sizes[2] == in_sizes[3]);
    if (interleaved) {
        for (int i = 0; i < 5; ++i) {
            W[i]  = (const float*)d_in[1 + 3*i];
            G[i]  = (const float*)d_in[2 + 3*i];
            Bv[i] = (const float*)d_in[3 + 3*i];
        }
    } else {
        for (int i = 0; i < 5; ++i) {
            W[i]  = (const float*)d_in[1 + i];
            G[i]  = (const float*)d_in[6 + i];
            Bv[i] = (const float*)d_in[11 + i];
        }
    }
    float* out = (float*)d_out;

    float *F0,*F1,*F2,*F3,*F4,*negd,*Y,*Wcat,*sq,*Y5; int* idx;
    cudaGetSymbolAddress((void**)&F0,   g_F0);
    cudaGetSymbolAddress((void**)&F1,   g_F1);
    cudaGetSymbolAddress((void**)&F2,   g_F2);
    cudaGetSymbolAddress((void**)&F3,   g_F3);
    cudaGetSymbolAddress((void**)&F4,   g_F4);
    cudaGetSymbolAddress((void**)&negd, g_negd);
    cudaGetSymbolAddress((void**)&Y,    g_Y);
    cudaGetSymbolAddress((void**)&Wcat, g_Wcat);
    cudaGetSymbolAddress((void**)&sq,   g_sq);
    cudaGetSymbolAddress((void**)&Y5,   g_Y5);
    cudaGetSymbolAddress((void**)&idx,  g_idx);

    transpose_in<<<(BB*3*NN + 255)/256, 256>>>(x, F0);

    struct Layer { const float* Fin; float* Fout; int C; int O; int wi; };
    Layer L[4] = {
        {F0, F1,   3,  64, 0},
        {F1, F2,  64,  64, 1},
        {F2, F3,  64, 128, 2},
        {F3, F4, 128, 256, 3},
    };

    for (int li = 0; li < 4; ++li) {
        int C = L[li].C, O = L[li].O;
        sqnorm_kernel<<<PTS/256, 256>>>(L[li].Fin, sq, C);
        gemm_nt<<<dim3(NN/64, NN/64, BB), 256>>>(
            L[li].Fin, L[li].Fin, negd, NN, NN, C,
            (size_t)NN*C, (size_t)NN*C, (size_t)NN*NN, sq, NN, 1);
        topk_radix<<<PTS, 256>>>(negd, idx);
        prep_wcat<<<(2*O*C + 255)/256, 256>>>(W[L[li].wi], Wcat, O, C);
        gemm_nt<<<dim3(2*O/64, PTS/64, 1), 256>>>(
            L[li].Fin, Wcat, Y, PTS, 2*O, C, 0, 0, 0, nullptr, 0, 0);
        edge_max<<<PTS, O>>>(Y, idx, G[L[li].wi], Bv[L[li].wi], L[li].Fout, O);
    }

    gemm_nt<<<dim3(1024/64, PTS/64, 1), 256>>>(
        F4, W[4], Y5, PTS, 1024, 256, 0, 0, 0, nullptr, 0, 0);
    final_max<<<dim3(BB, 1024/256), 256>>>(Y5, G[4], Bv[4], out);
}